// round 17
// baseline (speedup 1.0000x reference)
#include <cuda_runtime.h>
#include <cuda_bf16.h>

// NonLocalMeans: x [N,3,512,512] f32 -> out [N,3,512,512] f32
//   y = luminance(clip(x)); per shift s in [-5,5]^2:
//     D(p,s) = sum_{t in [-2,2]^2} (y(p+t) - y(p+t-s))^2   (circular)
//     w = exp(-sqrt(D)/3);  out(p) = clip( sum_s w * x(p-s) / sum_s w )

#define IMG_H 512
#define IMG_W 512
#define WMASK 511
#define TSZ   32
#define YDIM  46
#define YSTR  47
#define VSTR  40
#define SVSZ  (TSZ * VSTR)
#define XDIM  42
#define XSTR  44

// ---- phase 1: vertical 5-sums of squared luminance diffs, one shift ----
__device__ __forceinline__ void do_p1(const float* __restrict__ sy,
                                      float* __restrict__ svb,
                                      const float yreg[12],
                                      int ybase, int svbase,
                                      int sys, int sxs, bool act)
{
    if (!act) return;
    int off = ybase - sys * YSTR - sxs;   // Y(q - s)
    float d[12];
    #pragma unroll
    for (int k = 0; k < 12; ++k) {
        float t = yreg[k] - sy[off + k * YSTR];
        d[k] = t * t;
    }
    float v = d[0] + d[1] + d[2] + d[3] + d[4];
    svb[svbase] = v;
    #pragma unroll
    for (int k = 1; k < 8; ++k) {
        v += d[k + 4] - d[k - 1];
        svb[svbase + k * VSTR] = v;
    }
}

// ---- phase 2: horizontal 5-sum, weight, accumulate.  li = LI0 + k ----
template<int LI0>
__device__ __forceinline__ void do_p2(const float* __restrict__ svb, int eoff,
                                      const float xr_[9], const float xg_[9],
                                      const float xb_[9],
                                      float wacc[4], float accr[4],
                                      float accg[4], float accb[4])
{
    float4 a = *(const float4*)(svb + eoff);
    float4 b = *(const float4*)(svb + eoff + 4);
    float v[8] = {a.x, a.y, a.z, a.w, b.x, b.y, b.z, b.w};
    float D = v[0] + v[1] + v[2] + v[3] + v[4];
    #pragma unroll
    for (int k = 0; k < 4; ++k) {
        float Dk = fmaxf(D, 0.0f);                    // sliding sums can go -eps
        float sq;
        asm("sqrt.approx.f32 %0, %1;" : "=f"(sq) : "f"(Dk));
        float w;                                       // exp(-sq/3) = 2^(sq*-log2e/3)
        asm("ex2.approx.f32 %0, %1;" : "=f"(w) : "f"(sq * -0.48089834696f));
        wacc[k] += w;
        accr[k] = fmaf(w, xr_[LI0 + k], accr[k]);
        accg[k] = fmaf(w, xg_[LI0 + k], accg[k]);
        accb[k] = fmaf(w, xb_[LI0 + k], accb[k]);
        if (k < 3) D += v[k + 5] - v[k];
    }
}

__global__ __launch_bounds__(256, 3)
void nlm_kernel(const float* __restrict__ x, float* __restrict__ out)
{
    __shared__ __align__(16) float sy [YDIM * YSTR];   // luminance, halo 7
    __shared__ __align__(16) float sv [2 * SVSZ];      // double-buffered vert sums
    __shared__ __align__(16) float sxr[XDIM * XSTR];   // x channels, halo 5
    __shared__ __align__(16) float sxg[XDIM * XSTR];
    __shared__ __align__(16) float sxb[XDIM * XSTR];

    const int tid = threadIdx.x;
    const int gx0 = blockIdx.x * TSZ;
    const int gy0 = blockIdx.y * TSZ;
    const int n   = blockIdx.z;

    const float* xr = x + (size_t)n * 3 * IMG_H * IMG_W;
    const float* xg = xr + IMG_H * IMG_W;
    const float* xb = xg + IMG_H * IMG_W;

    // ---- load luminance tile (halo 7), circular wrap ----
    for (int idx = tid; idx < YDIM * YDIM; idx += 256) {
        int i = idx / YDIM, j = idx - i * YDIM;
        int g = ((gy0 + i - 7) & WMASK) * IMG_W + ((gx0 + j - 7) & WMASK);
        float r  = __saturatef(xr[g]);
        float gg = __saturatef(xg[g]);
        float b  = __saturatef(xb[g]);
        sy[i * YSTR + j] = 0.299f * r + 0.587f * gg + 0.114f * b;
    }
    // ---- load x tiles (halo 5) ----
    for (int idx = tid; idx < XDIM * XDIM; idx += 256) {
        int i = idx / XDIM, j = idx - i * XDIM;
        int g = ((gy0 + i - 5) & WMASK) * IMG_W + ((gx0 + j - 5) & WMASK);
        sxr[i * XSTR + j] = xr[g];
        sxg[i * XSTR + j] = xg[g];
        sxb[i * XSTR + j] = xb[g];
    }
    __syncthreads();

    // ---- phase-1 assignment: 144 threads = 36 cols x 4 row-segments(8) ----
    const int  p1s    = tid / 36;
    const int  p1j    = tid - p1s * 36;
    const bool p1act  = tid < 144;
    const int  ybase  = (8 * p1s + 5) * YSTR + (p1j + 5);
    const int  svbase = (8 * p1s) * VSTR + p1j;
    float yreg[12];
    if (p1act) {
        #pragma unroll
        for (int k = 0; k < 12; ++k) yreg[k] = sy[ybase + k * YSTR];
    }

    // ---- phase-2 assignment: thread owns 4 horizontally adjacent pixels ----
    const int prow = tid >> 3;
    const int pg   = tid & 7;
    const int eoff = prow * VSTR + 4 * pg;

    float wacc[4] = {0,0,0,0};
    float accr[4] = {0,0,0,0};
    float accg[4] = {0,0,0,0};
    float accb[4] = {0,0,0,0};

    // prologue: P1 for (sys=-5, sxs=-5) into buffer 0
    int buf = 0;
    do_p1(sy, sv, yreg, ybase, svbase, -5, -5, p1act);
    __syncthreads();

    #pragma unroll 1
    for (int sys_i = 0; sys_i < 11; ++sys_i) {
        const int sys = sys_i - 5;
        const int rb  = (prow + 5 - sys) * XSTR + 4 * pg;
        float xr_[9], xg_[9], xb_[9];

        // half-A x cache: cols [4pg+5 .. 4pg+13]  (li = k - sxs, sxs in [-5,0])
        {
            float4 a0 = *(const float4*)&sxr[rb + 4];
            float4 a1 = *(const float4*)&sxr[rb + 8];
            float4 a2 = *(const float4*)&sxr[rb + 12];
            xr_[0]=a0.y; xr_[1]=a0.z; xr_[2]=a0.w; xr_[3]=a1.x; xr_[4]=a1.y;
            xr_[5]=a1.z; xr_[6]=a1.w; xr_[7]=a2.x; xr_[8]=a2.y;
            float4 g0 = *(const float4*)&sxg[rb + 4];
            float4 g1 = *(const float4*)&sxg[rb + 8];
            float4 g2 = *(const float4*)&sxg[rb + 12];
            xg_[0]=g0.y; xg_[1]=g0.z; xg_[2]=g0.w; xg_[3]=g1.x; xg_[4]=g1.y;
            xg_[5]=g1.z; xg_[6]=g1.w; xg_[7]=g2.x; xg_[8]=g2.y;
            float4 b0 = *(const float4*)&sxb[rb + 4];
            float4 b1 = *(const float4*)&sxb[rb + 8];
            float4 b2 = *(const float4*)&sxb[rb + 12];
            xb_[0]=b0.y; xb_[1]=b0.z; xb_[2]=b0.w; xb_[3]=b1.x; xb_[4]=b1.y;
            xb_[5]=b1.z; xb_[6]=b1.w; xb_[7]=b2.x; xb_[8]=b2.y;
        }
        // sxs = -5..0 : produce next shift, consume current (LI0 = -sxs), literal args
#define STEP_A(SXS, LI0)                                                        \
        do {                                                                    \
            do_p1(sy, sv + (buf ^ 1) * SVSZ, yreg, ybase, svbase,               \
                  sys, (SXS) + 1, p1act);                                       \
            do_p2<LI0>(sv + buf * SVSZ, eoff, xr_, xg_, xb_,                    \
                       wacc, accr, accg, accb);                                 \
            buf ^= 1;                                                           \
            __syncthreads();                                                    \
        } while (0)
        STEP_A(-5, 5); STEP_A(-4, 4); STEP_A(-3, 3);
        STEP_A(-2, 2); STEP_A(-1, 1); STEP_A( 0, 0);
#undef STEP_A

        // half-B x cache: cols [4pg .. 4pg+7]  (li = k - sxs + 5, sxs in [1,5])
        {
            float4 a0 = *(const float4*)&sxr[rb];
            float4 a1 = *(const float4*)&sxr[rb + 4];
            xr_[0]=a0.x; xr_[1]=a0.y; xr_[2]=a0.z; xr_[3]=a0.w;
            xr_[4]=a1.x; xr_[5]=a1.y; xr_[6]=a1.z; xr_[7]=a1.w;
            float4 g0 = *(const float4*)&sxg[rb];
            float4 g1 = *(const float4*)&sxg[rb + 4];
            xg_[0]=g0.x; xg_[1]=g0.y; xg_[2]=g0.z; xg_[3]=g0.w;
            xg_[4]=g1.x; xg_[5]=g1.y; xg_[6]=g1.z; xg_[7]=g1.w;
            float4 b0 = *(const float4*)&sxb[rb];
            float4 b1 = *(const float4*)&sxb[rb + 4];
            xb_[0]=b0.x; xb_[1]=b0.y; xb_[2]=b0.z; xb_[3]=b0.w;
            xb_[4]=b1.x; xb_[5]=b1.y; xb_[6]=b1.z; xb_[7]=b1.w;
        }
        // sxs = 1..4 : next = (sys, sxs+1); LI0 = 5-sxs
#define STEP_B(SXS, LI0)                                                        \
        do {                                                                    \
            do_p1(sy, sv + (buf ^ 1) * SVSZ, yreg, ybase, svbase,               \
                  sys, (SXS) + 1, p1act);                                       \
            do_p2<LI0>(sv + buf * SVSZ, eoff, xr_, xg_, xb_,                    \
                       wacc, accr, accg, accb);                                 \
            buf ^= 1;                                                           \
            __syncthreads();                                                    \
        } while (0)
        STEP_B(1, 4); STEP_B(2, 3); STEP_B(3, 2); STEP_B(4, 1);
#undef STEP_B
        // sxs = 5 : next = (sys+1, -5) if any; LI0 = 0
        do_p1(sy, sv + (buf ^ 1) * SVSZ, yreg, ybase, svbase,
              sys + 1, -5, p1act && (sys_i < 10));
        do_p2<0>(sv + buf * SVSZ, eoff, xr_, xg_, xb_,
                 wacc, accr, accg, accb);
        buf ^= 1;
        __syncthreads();
    }

    // ---- write output ----
    float* outr = out + (size_t)n * 3 * IMG_H * IMG_W;
    int gbase = (gy0 + prow) * IMG_W + gx0 + 4 * pg;
    #pragma unroll
    for (int k = 0; k < 4; ++k) {
        float inv = __fdividef(1.0f, wacc[k]);         // wacc >= 1 (center w = 1)
        outr[gbase + k]                     = __saturatef(accr[k] * inv);
        outr[gbase + k + IMG_H * IMG_W]     = __saturatef(accg[k] * inv);
        outr[gbase + k + 2 * IMG_H * IMG_W] = __saturatef(accb[k] * inv);
    }
}

extern "C" void kernel_launch(void* const* d_in, const int* in_sizes, int n_in,
                              void* d_out, int out_size)
{
    const float* x = (const float*)d_in[0];
    float* out = (float*)d_out;
    int nbatch = in_sizes[0] / (3 * IMG_H * IMG_W);   // expect 2
    dim3 grid(IMG_W / TSZ, IMG_H / TSZ, nbatch);
    nlm_kernel<<<grid, 256>>>(x, out);
}